// round 1
// baseline (speedup 1.0000x reference)
#include <cuda_runtime.h>
#include <cstdint>

#define BB 16
#define HH 512
#define WW 512
#define HW (HH*WW)

// Scratch (no allocations allowed -> __device__ globals)
__device__ float         g_colsum[BB*HW];          // vertical 31-window sums
__device__ unsigned char g_mask  [BB*HW];          // remapped mask as u8
__device__ float         g_part  [BB*HH*4];        // per-(b,row) partial sums
__device__ int           g_is64;                   // mask dtype flag

// ---------------------------------------------------------------------------
// Detect whether mask buffer is int64 or int32.
// For int64 non-negative data, every odd 32-bit word is 0.
// For random 0/1 int32 data, many odd words are 1 (P[all zero] ~ 2^-2048).
// Reads only first 8192 int32 = 32KB (in-bounds for both layouts).
__global__ void detect_kernel(const int* __restrict__ m) {
    int s = 0;
    for (int i = threadIdx.x * 2 + 1; i < 8192; i += 64) s |= m[i];
    #pragma unroll
    for (int o = 16; o > 0; o >>= 1) s |= __shfl_down_sync(0xffffffffu, s, o);
    if (threadIdx.x == 0) g_is64 = (s == 0) ? 1 : 0;
}

// ---------------------------------------------------------------------------
// Pass 1: vertical sliding 31-sum of remapped mask -> g_colsum (f32),
// plus compact u8 mask copy -> g_mask.
// Grid: (B, 4 x-chunks, 8 y-segments of 64 rows), 128 threads (one column each).
__global__ void pass1_kernel(const int* __restrict__ mask32) {
    const int b   = blockIdx.x;
    const int x   = blockIdx.y * 128 + threadIdx.x;
    const int seg = blockIdx.z;
    const int ystart = seg * 64;
    const int yend   = ystart + 64;

    const int shift = g_is64;                    // 1 if int64 (stride-2 i32), 0 if int32
    const int* mb = mask32 + (((size_t)b * HW) << shift);
    float*         cs = g_colsum + (size_t)b * HW;
    unsigned char* mu = g_mask   + (size_t)b * HW;

    float sum = 0.f;
    // warm-up: rows [ystart-15, ystart+14]
    for (int yy = ystart - 15; yy < ystart + 15; ++yy) {
        if (yy >= 0 && yy < HH) {
            int v = mb[(size_t)(yy * WW + x) << shift];
            sum += (v == 255) ? 0.f : (float)v;
        }
    }
    for (int y = ystart; y < yend; ++y) {
        int yin = y + 15;
        if (yin < HH) {
            int v = mb[(size_t)(yin * WW + x) << shift];
            sum += (v == 255) ? 0.f : (float)v;
        }
        cs[y * WW + x] = sum;
        int yout = y - 15;
        if (yout >= 0) {
            int v = mb[(size_t)(yout * WW + x) << shift];
            sum -= (v == 255) ? 0.f : (float)v;
        }
    }
    // compact u8 mask for this segment (these rows are hot in L1/L2)
    for (int y = ystart; y < yend; ++y) {
        int v = mb[(size_t)(y * WW + x) << shift];
        mu[y * WW + x] = (unsigned char)((v == 255) ? 0 : v);
    }
}

// ---------------------------------------------------------------------------
// Pass 2: per-row horizontal window via shared prefix scan, fused with
// log-softmax CE + weighted IoU terms; deterministic block reduction of the
// 4 accumulators into g_part[(b*H+y)*4 + k].
// Grid: (H, B), 512 threads (one pixel each).
__global__ void pass2_kernel(const float* __restrict__ pred) {
    const int y = blockIdx.x;
    const int b = blockIdx.y;
    const int x = threadIdx.x;
    const int lane = x & 31, warp = x >> 5;

    __shared__ float P[WW];
    __shared__ float wsum[16];
    __shared__ float red[16][4];

    const size_t rowbase = (size_t)b * HW + (size_t)y * WW;

    // inclusive prefix scan of colsum row (exact: integer-valued <= 15872)
    float v = g_colsum[rowbase + x];
    #pragma unroll
    for (int o = 1; o < 32; o <<= 1) {
        float n = __shfl_up_sync(0xffffffffu, v, o);
        if (lane >= o) v += n;
    }
    if (lane == 31) wsum[warp] = v;
    __syncthreads();
    if (warp == 0) {
        float t = (lane < 16) ? wsum[lane] : 0.f;
        #pragma unroll
        for (int o = 1; o < 16; o <<= 1) {
            float n = __shfl_up_sync(0xffffffffu, t, o);
            if (lane >= o) t += n;
        }
        if (lane < 16) wsum[lane] = t;
    }
    __syncthreads();
    float pref = v + ((warp > 0) ? wsum[warp - 1] : 0.f);
    P[x] = pref;
    __syncthreads();

    const int hi = (x + 15 < WW - 1) ? (x + 15) : (WW - 1);
    float win = P[hi] - ((x >= 16) ? P[x - 16] : 0.f);
    float pooled = win * (1.0f / 961.0f);

    float mf = (float)g_mask[rowbase + x];

    const float* pb = pred + ((size_t)b * 2) * HW + (size_t)y * WW + x;
    float p0 = pb[0];
    float p1 = pb[HW];

    float mx = fmaxf(p0, p1);
    float e0 = __expf(p0 - mx), e1 = __expf(p1 - mx);
    float lse = mx + __logf(e0 + e1);
    float logp0 = p0 - lse, logp1 = p1 - lse;

    float wbce = (mf > 0.5f) ? -logp1 : -logp0;
    float p1p  = __expf(logp1);
    float weit = 1.0f + 5.0f * fabsf(pooled - mf);

    float a0 = weit;                 // weit_sum
    float a1 = weit * wbce;          // weighted BCE
    float a2 = p1p * mf * weit;      // inter
    float a3 = (p1p + mf) * weit;    // cardinality

    // block reduce (deterministic)
    #pragma unroll
    for (int o = 16; o > 0; o >>= 1) {
        a0 += __shfl_down_sync(0xffffffffu, a0, o);
        a1 += __shfl_down_sync(0xffffffffu, a1, o);
        a2 += __shfl_down_sync(0xffffffffu, a2, o);
        a3 += __shfl_down_sync(0xffffffffu, a3, o);
    }
    if (lane == 0) { red[warp][0] = a0; red[warp][1] = a1; red[warp][2] = a2; red[warp][3] = a3; }
    __syncthreads();
    if (warp == 0) {
        float r0 = (lane < 16) ? red[lane][0] : 0.f;
        float r1 = (lane < 16) ? red[lane][1] : 0.f;
        float r2 = (lane < 16) ? red[lane][2] : 0.f;
        float r3 = (lane < 16) ? red[lane][3] : 0.f;
        #pragma unroll
        for (int o = 8; o > 0; o >>= 1) {
            r0 += __shfl_down_sync(0xffffffffu, r0, o);
            r1 += __shfl_down_sync(0xffffffffu, r1, o);
            r2 += __shfl_down_sync(0xffffffffu, r2, o);
            r3 += __shfl_down_sync(0xffffffffu, r3, o);
        }
        if (lane == 0) {
            float* out = g_part + ((size_t)b * HH + y) * 4;
            out[0] = r0; out[1] = r1; out[2] = r2; out[3] = r3;
        }
    }
}

// ---------------------------------------------------------------------------
// Pass 3: one block, warp w reduces batch w's 512 row-partials; combine
// wbce + wiou per batch; mean over batch -> out[0].
__global__ void pass3_kernel(float* __restrict__ out) {
    const int lane = threadIdx.x & 31;
    const int b    = threadIdx.x >> 5;   // 16 warps = 16 batches

    float s0 = 0.f, s1 = 0.f, s2 = 0.f, s3 = 0.f;
    for (int y = lane; y < HH; y += 32) {
        const float* p = g_part + ((size_t)b * HH + y) * 4;
        s0 += p[0]; s1 += p[1]; s2 += p[2]; s3 += p[3];
    }
    #pragma unroll
    for (int o = 16; o > 0; o >>= 1) {
        s0 += __shfl_down_sync(0xffffffffu, s0, o);
        s1 += __shfl_down_sync(0xffffffffu, s1, o);
        s2 += __shfl_down_sync(0xffffffffu, s2, o);
        s3 += __shfl_down_sync(0xffffffffu, s3, o);
    }
    __shared__ float lossb[16];
    if (lane == 0) {
        float wbce  = s1 / s0;
        float inter = s2;
        float uni   = s3 - s2;           // cardinality - inter
        float wiou  = 1.f - (inter + 1.f) / (uni + 1.f);
        lossb[b] = wbce + wiou;
    }
    __syncthreads();
    if (threadIdx.x == 0) {
        float t = 0.f;
        #pragma unroll
        for (int i = 0; i < 16; ++i) t += lossb[i];
        out[0] = t * (1.f / 16.f);
    }
}

// ---------------------------------------------------------------------------
extern "C" void kernel_launch(void* const* d_in, const int* in_sizes, int n_in,
                              void* d_out, int out_size) {
    const float* pred   = (const float*)d_in[0];
    const int*   mask32 = (const int*)d_in[1];   // viewed as 32-bit words; dtype detected
    float* out = (float*)d_out;

    detect_kernel<<<1, 64>>>(mask32);
    pass1_kernel<<<dim3(BB, 4, 8), 128>>>(mask32);
    pass2_kernel<<<dim3(HH, BB), 512>>>(pred);
    pass3_kernel<<<1, 512>>>(out);
}